// round 2
// baseline (speedup 1.0000x reference)
#include <cuda_runtime.h>
#include <math.h>

#define Bdim 2
#define Ndim 1024
#define Ddim 1024
#define Hdim 16
#define Sdim 4
#define DHdim 64
#define NNdim (Ndim*Ndim)

// ---------------- static scratch (no allocation allowed) ----------------
__device__ float g_q[Sdim*Bdim*Ndim*Ddim];        // 32 MB
__device__ float g_k[Sdim*Bdim*Ndim*Ddim];        // 32 MB
__device__ float g_v[Sdim*Bdim*Ndim*Ddim];        // 32 MB
__device__ float g_p[(size_t)Sdim*Bdim*Hdim*NNdim]; // 512 MB probs
__device__ float g_outs[Sdim*Bdim*Ndim*Ddim];     // 32 MB per-sample attn out
__device__ float g_comb[Bdim*Ndim*Ddim];          // 8 MB combined
__device__ float g_xmean[Bdim*Ddim];
__device__ float g_params[16];                    // [0]=1/temp, [1..4]=gw, [5..12]=coh[b][s]

// ---------------- mean pool over tokens ----------------
__global__ void xmean_kernel(const float* __restrict__ x) {
    int idx = blockIdx.x * blockDim.x + threadIdx.x;  // b*D + d
    if (idx >= Bdim * Ddim) return;
    int b = idx / Ddim, d = idx % Ddim;
    const float* p = x + (long long)b * Ndim * Ddim + d;
    float acc = 0.f;
    for (int n = 0; n < Ndim; n++) acc += p[(long long)n * Ddim];
    g_xmean[idx] = acc * (1.0f / Ndim);
}

// ---------------- temp clip, gate weights, coherence gate ----------------
__global__ void prep_kernel(const float* __restrict__ Wg, const float* __restrict__ bg,
                            const float* __restrict__ hyp_w,
                            const float* __restrict__ temperature) {
    int t = threadIdx.x;
    int warp = t / 32, lane = t % 32;
    if (warp < Bdim * Sdim) {
        int b = warp / Sdim, s = warp % Sdim;
        float acc = 0.f;
        for (int d = lane; d < Ddim; d += 32)
            acc += g_xmean[b * Ddim + d] * Wg[s * Ddim + d];
        #pragma unroll
        for (int o = 16; o > 0; o >>= 1) acc += __shfl_down_sync(0xffffffff, acc, o);
        if (lane == 0) {
            float vv = acc + bg[s];
            g_params[5 + b * Sdim + s] = 1.0f / (1.0f + expf(-vv));
        }
    }
    if (t == 0) {
        float tp = fminf(fmaxf(temperature[0], 0.1f), 10.0f);
        g_params[0] = 1.0f / tp;
        float hw[Sdim];
        float m = -1e30f;
        for (int s = 0; s < Sdim; s++) { hw[s] = hyp_w[s] / tp; m = fmaxf(m, hw[s]); }
        float sum = 0.f;
        for (int s = 0; s < Sdim; s++) { hw[s] = expf(hw[s] - m); sum += hw[s]; }
        for (int s = 0; s < Sdim; s++) g_params[1 + s] = hw[s] / sum;
    }
}

// ---------------- generic batched C = alpha * A * B^T (+bias) ----------------
// A: [M,K] row-major (lda), Bt: [N,K] row-major (ldb), C: [M,N] row-major (ldc)
// per-batch offsets: offX = (z % zmod)*sXlo + (z / zmod)*sXhi ; offC = z*sC
// M, N multiples of 64; K multiple of 16.
__global__ void __launch_bounds__(256) gemm_ABt(
    const float* __restrict__ Aall, const float* __restrict__ Ball,
    float* __restrict__ Call, const float* __restrict__ bias,
    int K, int lda, int ldb, int ldc,
    int zmod, long long sAlo, long long sAhi,
    long long sBlo, long long sBhi, long long sC, float alpha)
{
    int z = blockIdx.z;
    const float* A  = Aall + (long long)(z % zmod) * sAlo + (long long)(z / zmod) * sAhi;
    const float* Bt = Ball + (long long)(z % zmod) * sBlo + (long long)(z / zmod) * sBhi;
    float* C = Call + (long long)z * sC;

    int m0 = blockIdx.y * 64;
    int n0 = blockIdx.x * 64;
    __shared__ float As[16][65];
    __shared__ float Bs[16][65];
    int tid = threadIdx.x;
    int tx = tid % 16, ty = tid / 16;
    int lk = tid % 16, lm4 = tid / 16;
    float acc[4][4] = {};

    for (int k0 = 0; k0 < K; k0 += 16) {
        #pragma unroll
        for (int i = 0; i < 4; i++) {
            int m = lm4 * 4 + i;
            As[lk][m] = A [(long long)(m0 + m) * lda + k0 + lk];
            Bs[lk][m] = Bt[(long long)(n0 + m) * ldb + k0 + lk];
        }
        __syncthreads();
        #pragma unroll
        for (int k = 0; k < 16; k++) {
            float a[4], b[4];
            #pragma unroll
            for (int i = 0; i < 4; i++) a[i] = As[k][ty * 4 + i];
            #pragma unroll
            for (int j = 0; j < 4; j++) b[j] = Bs[k][tx * 4 + j];
            #pragma unroll
            for (int i = 0; i < 4; i++)
                #pragma unroll
                for (int j = 0; j < 4; j++) acc[i][j] += a[i] * b[j];
        }
        __syncthreads();
    }
    #pragma unroll
    for (int i = 0; i < 4; i++) {
        int m = m0 + ty * 4 + i;
        #pragma unroll
        for (int j = 0; j < 4; j++) {
            int n = n0 + tx * 4 + j;
            float val = acc[i][j] * alpha;
            if (bias) val += bias[n];
            C[(long long)m * ldc + n] = val;
        }
    }
}

// ---------------- softmax over each probs row (in place) ----------------
__global__ void softmax_kernel() {
    long long row = blockIdx.x;
    float* r = g_p + row * Ndim;
    float invT = g_params[0];
    __shared__ float red[256];
    int t = threadIdx.x;
    float v[4];
    float mx = -1e30f;
    #pragma unroll
    for (int i = 0; i < 4; i++) { v[i] = r[t + i * 256] * invT; mx = fmaxf(mx, v[i]); }
    red[t] = mx; __syncthreads();
    for (int s = 128; s > 0; s >>= 1) { if (t < s) red[t] = fmaxf(red[t], red[t + s]); __syncthreads(); }
    mx = red[0]; __syncthreads();
    float sm = 0.f;
    #pragma unroll
    for (int i = 0; i < 4; i++) { v[i] = __expf(v[i] - mx); sm += v[i]; }
    red[t] = sm; __syncthreads();
    for (int s = 128; s > 0; s >>= 1) { if (t < s) red[t] += red[t + s]; __syncthreads(); }
    float inv = 1.0f / red[0];
    #pragma unroll
    for (int i = 0; i < 4; i++) r[t + i * 256] = v[i] * inv;
}

// ---------------- combined_attn.mean(h): out2[b,i,j] = (1/H) sum_{s,h} gw[s] p ----------------
__global__ void reduce_attn_kernel(float* __restrict__ outAttn) {
    long long idx = (long long)blockIdx.x * blockDim.x + threadIdx.x;
    if (idx >= (long long)Bdim * NNdim) return;
    int b = (int)(idx / NNdim);
    long long rem = idx % NNdim;
    float acc = 0.f;
    #pragma unroll
    for (int s = 0; s < Sdim; s++) {
        float g = g_params[1 + s];
        const float* base = g_p + ((long long)(s * Bdim + b) * Hdim) * NNdim + rem;
        float hs = 0.f;
        for (int h = 0; h < Hdim; h++) hs += base[(long long)h * NNdim];
        acc += g * hs;
    }
    outAttn[idx] = acc * (1.0f / Hdim);
}

// ---------------- P @ V per (s,b,h): 64 i-rows x 64 dh per block ----------------
__global__ void __launch_bounds__(256) pv_kernel() {
    int z  = blockIdx.y;           // (s*B + b)*H + h
    int sb = z / Hdim, h = z % Hdim;
    const float* P = g_p + (long long)z * NNdim;
    const float* V = g_v + (long long)sb * Ndim * Ddim + h * DHdim;
    float* O = g_outs + (long long)sb * Ndim * Ddim + h * DHdim;
    int m0 = blockIdx.x * 64;

    __shared__ float Ps[16][65];
    __shared__ float Vs[16][64];
    int tid = threadIdx.x;
    int tx = tid % 16, ty = tid / 16;
    float acc[4][4] = {};
    int lk = tid % 16, lm4 = tid / 16;
    int vn = tid % 64, vk0 = tid / 64;   // 4 k-rows per thread

    for (int k0 = 0; k0 < Ndim; k0 += 16) {
        #pragma unroll
        for (int i = 0; i < 4; i++) {
            int m = lm4 * 4 + i;
            Ps[lk][m] = P[(long long)(m0 + m) * Ndim + k0 + lk];
        }
        #pragma unroll
        for (int i = 0; i < 4; i++) {
            int kk = vk0 + i * 4;
            Vs[kk][vn] = V[(long long)(k0 + kk) * Ddim + vn];
        }
        __syncthreads();
        #pragma unroll
        for (int k = 0; k < 16; k++) {
            float a[4], b[4];
            #pragma unroll
            for (int i = 0; i < 4; i++) a[i] = Ps[k][ty * 4 + i];
            #pragma unroll
            for (int j = 0; j < 4; j++) b[j] = Vs[k][tx * 4 + j];
            #pragma unroll
            for (int i = 0; i < 4; i++)
                #pragma unroll
                for (int j = 0; j < 4; j++) acc[i][j] += a[i] * b[j];
        }
        __syncthreads();
    }
    #pragma unroll
    for (int i = 0; i < 4; i++) {
        int m = m0 + ty * 4 + i;
        #pragma unroll
        for (int j = 0; j < 4; j++)
            O[(long long)m * Ddim + tx * 4 + j] = acc[i][j];
    }
}

// ---------------- combined[b,i,d] = sum_s gw[s]*coh[b,s]*outs[s,b,i,d] ----------------
__global__ void combine_kernel() {
    long long idx = (long long)blockIdx.x * blockDim.x + threadIdx.x;
    if (idx >= (long long)Bdim * Ndim * Ddim) return;
    int b = (int)(idx / ((long long)Ndim * Ddim));
    long long rem = idx % ((long long)Ndim * Ddim);
    float acc = 0.f;
    #pragma unroll
    for (int s = 0; s < Sdim; s++) {
        float w = g_params[1 + s] * g_params[5 + b * Sdim + s];
        acc += w * g_outs[(long long)(s * Bdim + b) * Ndim * Ddim + rem];
    }
    g_comb[idx] = acc;
}

// ---------------- launch ----------------
extern "C" void kernel_launch(void* const* d_in, const int* in_sizes, int n_in,
                              void* d_out, int out_size) {
    const float* x    = (const float*)d_in[0];
    const float* Wq   = (const float*)d_in[1];
    const float* Wk   = (const float*)d_in[2];
    const float* Wv   = (const float*)d_in[3];
    const float* Wg   = (const float*)d_in[4];
    const float* bg   = (const float*)d_in[5];
    const float* Wo   = (const float*)d_in[6];
    const float* bo   = (const float*)d_in[7];
    const float* hw   = (const float*)d_in[8];
    const float* temp = (const float*)d_in[9];
    float* out = (float*)d_out;

    float *q, *k, *v, *comb;
    cudaGetSymbolAddress((void**)&q, g_q);
    cudaGetSymbolAddress((void**)&k, g_k);
    cudaGetSymbolAddress((void**)&v, g_v);
    cudaGetSymbolAddress((void**)&comb, g_comb);

    const long long ND = (long long)Ndim * Ddim;
    const long long DD = (long long)Ddim * Ddim;

    // 1) mean pool + gates
    xmean_kernel<<<(Bdim * Ddim + 255) / 256, 256>>>(x);
    prep_kernel<<<1, 256>>>(Wg, bg, hw, temp);

    // 2) projections: q/k/v[s,b] = x[b] @ W[s]^T   (z = s*B + b)
    dim3 gproj(Ndim / 64, Ndim / 64, Sdim * Bdim);
    gemm_ABt<<<gproj, 256>>>(x, Wq, q, nullptr, Ddim, Ddim, Ddim, Ddim,
                             Bdim, ND, 0LL, 0LL, DD, ND, 1.0f);
    gemm_ABt<<<gproj, 256>>>(x, Wk, k, nullptr, Ddim, Ddim, Ddim, Ddim,
                             Bdim, ND, 0LL, 0LL, DD, ND, 1.0f);
    gemm_ABt<<<gproj, 256>>>(x, Wv, v, nullptr, Ddim, Ddim, Ddim, Ddim,
                             Bdim, ND, 0LL, 0LL, DD, ND, 1.0f);

    // 3) dots[s,b,h] = scale * Q K^T   (z = (s*B+b)*H + h)
    float* p;
    cudaGetSymbolAddress((void**)&p, g_p);
    dim3 gdots(Ndim / 64, Ndim / 64, Sdim * Bdim * Hdim);
    gemm_ABt<<<gdots, 256>>>(q, k, p, nullptr, DHdim, Ddim, Ddim, Ndim,
                             Hdim, (long long)DHdim, ND, (long long)DHdim, ND,
                             (long long)NNdim, 0.125f /* DH^-0.5 */);

    // 4) softmax rows (temp folded in)
    softmax_kernel<<<Sdim * Bdim * Hdim * Ndim, 256>>>();

    // 5) combined_attn mean over h -> second output
    reduce_attn_kernel<<<(unsigned)((Bdim * (long long)NNdim + 255) / 256), 256>>>(
        out + (long long)Bdim * ND);

    // 6) P @ V per (s,b,h)
    dim3 gpv(Ndim / 64, Sdim * Bdim * Hdim);
    pv_kernel<<<gpv, 256>>>();

    // 7) gate + hypothesis combine
    combine_kernel<<<(unsigned)((Bdim * ND + 255) / 256), 256>>>();

    // 8) y = combined @ Wo^T + bo -> first output
    dim3 gfin(Ndim / 64, Ndim / 64, Bdim);
    gemm_ABt<<<gfin, 256>>>(comb, Wo, out, bo, Ddim, Ddim, Ddim, Ddim,
                            1, 0LL, ND, 0LL, 0LL, ND, 1.0f);
}

// round 4
// speedup vs baseline: 3.0951x; 3.0951x over previous
#include <cuda_runtime.h>
#include <math.h>

#define Bdim 2
#define Ndim 1024
#define Ddim 1024
#define Hdim 16
#define Sdim 4
#define DHdim 64
#define NNdim (Ndim*Ndim)
#define KT 32

// ---------------- static scratch (no allocation allowed) ----------------
__device__ float g_q[Sdim*Bdim*Ndim*Ddim];          // 32 MB
__device__ float g_k[Sdim*Bdim*Ndim*Ddim];          // 32 MB
__device__ float g_v[Sdim*Bdim*Ndim*Ddim];          // 32 MB
__device__ float g_p[(size_t)Sdim*Bdim*Hdim*NNdim]; // 512 MB probs
__device__ float g_outs[Sdim*Bdim*Ndim*Ddim];       // 32 MB per-sample attn out
__device__ float g_comb[Bdim*Ndim*Ddim];            // 8 MB combined
__device__ float g_xmean[Bdim*Ddim];
__device__ float g_params[16];                      // [0]=1/temp, [1..4]=gw, [5..12]=coh[b][s]

// ---------------- helpers ----------------
__device__ __forceinline__ unsigned f2tf32(float x) {
    unsigned u;
    asm("cvt.rna.tf32.f32 %0, %1;" : "=r"(u) : "f"(x));
    return u;
}

__device__ __forceinline__ void mma_tf32(float* d, const unsigned* a, const unsigned* b) {
    asm volatile(
        "mma.sync.aligned.m16n8k8.row.col.f32.tf32.tf32.f32 "
        "{%0,%1,%2,%3},{%4,%5,%6,%7},{%8,%9},{%0,%1,%2,%3};"
        : "+f"(d[0]), "+f"(d[1]), "+f"(d[2]), "+f"(d[3])
        : "r"(a[0]), "r"(a[1]), "r"(a[2]), "r"(a[3]), "r"(b[0]), "r"(b[1]));
}

// ---------------- mean pool over tokens ----------------
__global__ void xmean_kernel(const float* __restrict__ x) {
    int idx = blockIdx.x * blockDim.x + threadIdx.x;  // b*D + d
    if (idx >= Bdim * Ddim) return;
    int b = idx / Ddim, d = idx % Ddim;
    const float* p = x + (long long)b * Ndim * Ddim + d;
    float acc = 0.f;
    for (int n = 0; n < Ndim; n++) acc += p[(long long)n * Ddim];
    g_xmean[idx] = acc * (1.0f / Ndim);
}

// ---------------- temp clip, gate weights, coherence gate ----------------
__global__ void prep_kernel(const float* __restrict__ Wg, const float* __restrict__ bg,
                            const float* __restrict__ hyp_w,
                            const float* __restrict__ temperature) {
    int t = threadIdx.x;
    int warp = t / 32, lane = t % 32;
    if (warp < Bdim * Sdim) {
        int b = warp / Sdim, s = warp % Sdim;
        float acc = 0.f;
        for (int d = lane; d < Ddim; d += 32)
            acc += g_xmean[b * Ddim + d] * Wg[s * Ddim + d];
        #pragma unroll
        for (int o = 16; o > 0; o >>= 1) acc += __shfl_down_sync(0xffffffff, acc, o);
        if (lane == 0) {
            float vv = acc + bg[s];
            g_params[5 + b * Sdim + s] = 1.0f / (1.0f + expf(-vv));
        }
    }
    if (t == 0) {
        float tp = fminf(fmaxf(temperature[0], 0.1f), 10.0f);
        g_params[0] = 1.0f / tp;
        float hw[Sdim];
        float m = -1e30f;
        for (int s = 0; s < Sdim; s++) { hw[s] = hyp_w[s] / tp; m = fmaxf(m, hw[s]); }
        float sum = 0.f;
        for (int s = 0; s < Sdim; s++) { hw[s] = expf(hw[s] - m); sum += hw[s]; }
        for (int s = 0; s < Sdim; s++) g_params[1 + s] = hw[s] / sum;
    }
}

// ---------------- tensor-core batched GEMM ----------------
// TRANSB=true : C = alpha * A * B^T, B given as [N,K] row-major (ldb)
// TRANSB=false: C = alpha * A * B,   B given as [K,N] row-major (ldb)
// A: [M,K] row-major (lda), C: [M,N] row-major (ldc)
// offsets: offX = (z % zmod)*sXlo + (z / zmod)*sXhi
template<int BM, int BN, int WM, int WN, bool TRANSB>
__global__ void __launch_bounds__(256) gemm_tc(
    const float* __restrict__ Aall, const float* __restrict__ Ball,
    float* __restrict__ Call, const float* __restrict__ bias,
    int K, int lda, int ldb, int ldc,
    int zmod, long long sAlo, long long sAhi,
    long long sBlo, long long sBhi, long long sClo, long long sChi, float alpha)
{
    constexpr int WARPS = (BM / WM) * (BN / WN);
    constexpr int THREADS = WARPS * 32;
    static_assert(THREADS == 256, "config");
    constexpr int MT = WM / 16, NT = WN / 8;
    constexpr int LDP = 36;                 // padded row stride for [rows][K] tiles
    constexpr int LDB2 = 72;                // padded row stride for [K][N] B tiles
    constexpr int RPP = THREADS / 8;        // 32 rows per pass ([rows][32] loads)
    constexpr int AI = BM / RPP;
    // B loader geometry
    constexpr int CG  = BN / 4;                            // float4 col-groups (NT path)
    constexpr int BLOADS = TRANSB ? (BN / RPP) : (KT / (THREADS / CG));
    constexpr int KPP = THREADS / CG;                      // k-rows per pass (NT path)
    constexpr int BSZ = TRANSB ? (BN * LDP) : (KT * LDB2); // smem floats per B buffer

    extern __shared__ float sm[];
    float* As = sm;                         // [2][BM][LDP]
    float* Bs = sm + 2 * BM * LDP;          // [2][BSZ]

    int z = blockIdx.z;
    const float* A  = Aall + (long long)(z % zmod) * sAlo + (long long)(z / zmod) * sAhi;
    const float* Bt = Ball + (long long)(z % zmod) * sBlo + (long long)(z / zmod) * sBhi;
    float* C = Call + (long long)(z % zmod) * sClo + (long long)(z / zmod) * sChi;

    int m0 = blockIdx.y * BM;
    int n0 = blockIdx.x * BN;
    int t = threadIdx.x;
    int lane = t & 31, w = t >> 5;
    int wr = w / (BN / WN), wc = w % (BN / WN);
    int lcol = (t & 7) * 4;                 // float col within K-tile
    int lrow = t >> 3;
    int browk = t / CG;                     // NT path: k row
    int bcol  = (t % CG) * 4;               // NT path: n col

    float acc[MT][NT][4];
    #pragma unroll
    for (int mt = 0; mt < MT; mt++)
        #pragma unroll
        for (int nt = 0; nt < NT; nt++)
            #pragma unroll
            for (int i = 0; i < 4; i++) acc[mt][nt][i] = 0.f;

    const int numT = K / KT;
    float4 ra[AI], rb[BLOADS];

    auto loadG = [&](int kt) {
        #pragma unroll
        for (int i = 0; i < AI; i++) {
            int r = lrow + i * RPP;
            ra[i] = *(const float4*)(A + (long long)(m0 + r) * lda + kt * KT + lcol);
        }
        if constexpr (TRANSB) {
            #pragma unroll
            for (int i = 0; i < BLOADS; i++) {
                int r = lrow + i * RPP;
                rb[i] = *(const float4*)(Bt + (long long)(n0 + r) * ldb + kt * KT + lcol);
            }
        } else {
            #pragma unroll
            for (int i = 0; i < BLOADS; i++) {
                int kk = browk + i * KPP;
                rb[i] = *(const float4*)(Bt + (long long)(kt * KT + kk) * ldb + n0 + bcol);
            }
        }
    };
    auto storeS = [&](int buf) {
        #pragma unroll
        for (int i = 0; i < AI; i++) {
            int r = lrow + i * RPP;
            unsigned* d = (unsigned*)(As + buf * BM * LDP + r * LDP + lcol);
            d[0] = f2tf32(ra[i].x); d[1] = f2tf32(ra[i].y);
            d[2] = f2tf32(ra[i].z); d[3] = f2tf32(ra[i].w);
        }
        if constexpr (TRANSB) {
            #pragma unroll
            for (int i = 0; i < BLOADS; i++) {
                int r = lrow + i * RPP;
                unsigned* d = (unsigned*)(Bs + buf * BSZ + r * LDP + lcol);
                d[0] = f2tf32(rb[i].x); d[1] = f2tf32(rb[i].y);
                d[2] = f2tf32(rb[i].z); d[3] = f2tf32(rb[i].w);
            }
        } else {
            #pragma unroll
            for (int i = 0; i < BLOADS; i++) {
                int kk = browk + i * KPP;
                unsigned* d = (unsigned*)(Bs + buf * BSZ + kk * LDB2 + bcol);
                d[0] = f2tf32(rb[i].x); d[1] = f2tf32(rb[i].y);
                d[2] = f2tf32(rb[i].z); d[3] = f2tf32(rb[i].w);
            }
        }
    };

    loadG(0);
    storeS(0);

    int g = lane >> 2, c4 = lane & 3;
    for (int kt = 0; kt < numT; kt++) {
        __syncthreads();
        int buf = kt & 1;
        if (kt + 1 < numT) loadG(kt + 1);

        const float* Ab = As + buf * BM * LDP;
        const float* Bb = Bs + buf * BSZ;
        #pragma unroll
        for (int ks = 0; ks < KT / 8; ks++) {
            int kb = ks * 8 + c4;
            unsigned afr[MT][4], bfr[NT][2];
            #pragma unroll
            for (int mt = 0; mt < MT; mt++) {
                const float* pA = Ab + (wr * WM + mt * 16 + g) * LDP;
                afr[mt][0] = __float_as_uint(pA[kb]);
                afr[mt][1] = __float_as_uint(pA[8 * LDP + kb]);
                afr[mt][2] = __float_as_uint(pA[kb + 4]);
                afr[mt][3] = __float_as_uint(pA[8 * LDP + kb + 4]);
            }
            #pragma unroll
            for (int nt = 0; nt < NT; nt++) {
                if constexpr (TRANSB) {
                    const float* pB = Bb + (wc * WN + nt * 8 + g) * LDP;
                    bfr[nt][0] = __float_as_uint(pB[kb]);
                    bfr[nt][1] = __float_as_uint(pB[kb + 4]);
                } else {
                    int n = wc * WN + nt * 8 + g;
                    bfr[nt][0] = __float_as_uint(Bb[kb * LDB2 + n]);
                    bfr[nt][1] = __float_as_uint(Bb[(kb + 4) * LDB2 + n]);
                }
            }
            #pragma unroll
            for (int mt = 0; mt < MT; mt++)
                #pragma unroll
                for (int nt = 0; nt < NT; nt++)
                    mma_tf32(acc[mt][nt], afr[mt], bfr[nt]);
        }
        if (kt + 1 < numT) storeS(1 - buf);
    }

    // epilogue
    #pragma unroll
    for (int mt = 0; mt < MT; mt++) {
        int r = m0 + wr * WM + mt * 16 + g;
        #pragma unroll
        for (int nt = 0; nt < NT; nt++) {
            int c = n0 + wc * WN + nt * 8 + c4 * 2;
            float b0 = 0.f, b1 = 0.f;
            if (bias) { b0 = bias[c]; b1 = bias[c + 1]; }
            float2 v0 = make_float2(acc[mt][nt][0] * alpha + b0,
                                    acc[mt][nt][1] * alpha + b1);
            float2 v1 = make_float2(acc[mt][nt][2] * alpha + b0,
                                    acc[mt][nt][3] * alpha + b1);
            *(float2*)(C + (long long)r * ldc + c) = v0;
            *(float2*)(C + (long long)(r + 8) * ldc + c) = v1;
        }
    }
}

// ---------------- softmax over each probs row (in place) ----------------
__global__ void softmax_kernel() {
    long long row = blockIdx.x;
    float* r = g_p + row * Ndim;
    float invT = g_params[0];
    __shared__ float red[256];
    int t = threadIdx.x;
    float v[4];
    float mx = -1e30f;
    #pragma unroll
    for (int i = 0; i < 4; i++) { v[i] = r[t + i * 256] * invT; mx = fmaxf(mx, v[i]); }
    red[t] = mx; __syncthreads();
    for (int s = 128; s > 0; s >>= 1) { if (t < s) red[t] = fmaxf(red[t], red[t + s]); __syncthreads(); }
    mx = red[0]; __syncthreads();
    float sm = 0.f;
    #pragma unroll
    for (int i = 0; i < 4; i++) { v[i] = __expf(v[i] - mx); sm += v[i]; }
    red[t] = sm; __syncthreads();
    for (int s = 128; s > 0; s >>= 1) { if (t < s) red[t] += red[t + s]; __syncthreads(); }
    float inv = 1.0f / red[0];
    #pragma unroll
    for (int i = 0; i < 4; i++) r[t + i * 256] = v[i] * inv;
}

// ---------------- combined_attn.mean(h): out2[b,i,j] = (1/H) sum_{s,h} gw[s] p ----------------
__global__ void reduce_attn_kernel(float* __restrict__ outAttn) {
    long long idx = (long long)blockIdx.x * blockDim.x + threadIdx.x;
    if (idx >= (long long)Bdim * NNdim) return;
    int b = (int)(idx / NNdim);
    long long rem = idx % NNdim;
    float acc = 0.f;
    #pragma unroll
    for (int s = 0; s < Sdim; s++) {
        float gwv = g_params[1 + s];
        const float* base = g_p + ((long long)(s * Bdim + b) * Hdim) * NNdim + rem;
        float hs = 0.f;
        for (int h = 0; h < Hdim; h++) hs += base[(long long)h * NNdim];
        acc += gwv * hs;
    }
    outAttn[idx] = acc * (1.0f / Hdim);
}

// ---------------- combined[b,i,d] = sum_s gw[s]*coh[b,s]*outs[s,b,i,d] ----------------
__global__ void combine_kernel() {
    long long idx = (long long)blockIdx.x * blockDim.x + threadIdx.x;
    if (idx >= (long long)Bdim * Ndim * Ddim) return;
    int b = (int)(idx / ((long long)Ndim * Ddim));
    long long rem = idx % ((long long)Ndim * Ddim);
    float acc = 0.f;
    #pragma unroll
    for (int s = 0; s < Sdim; s++) {
        float w = g_params[1 + s] * g_params[5 + b * Sdim + s];
        acc += w * g_outs[(long long)(s * Bdim + b) * Ndim * Ddim + rem];
    }
    g_comb[idx] = acc;
}

// ---------------- launch ----------------
extern "C" void kernel_launch(void* const* d_in, const int* in_sizes, int n_in,
                              void* d_out, int out_size) {
    const float* x    = (const float*)d_in[0];
    const float* Wq   = (const float*)d_in[1];
    const float* Wk   = (const float*)d_in[2];
    const float* Wv   = (const float*)d_in[3];
    const float* Wg   = (const float*)d_in[4];
    const float* bg   = (const float*)d_in[5];
    const float* Wo   = (const float*)d_in[6];
    const float* bo   = (const float*)d_in[7];
    const float* hw   = (const float*)d_in[8];
    const float* temp = (const float*)d_in[9];
    float* out = (float*)d_out;

    float *q, *k, *v, *comb, *p, *outs;
    cudaGetSymbolAddress((void**)&q, g_q);
    cudaGetSymbolAddress((void**)&k, g_k);
    cudaGetSymbolAddress((void**)&v, g_v);
    cudaGetSymbolAddress((void**)&comb, g_comb);
    cudaGetSymbolAddress((void**)&p, g_p);
    cudaGetSymbolAddress((void**)&outs, g_outs);

    const long long ND = (long long)Ndim * Ddim;
    const long long DD = (long long)Ddim * Ddim;

    const int smem_sq = 2 * (128 + 128) * 36 * (int)sizeof(float);          // 73728
    const int smem_pv = (2 * 128 * 36 + 2 * KT * 72) * (int)sizeof(float);  // 55296
    cudaFuncSetAttribute(gemm_tc<128,128,64,32,true>,
                         cudaFuncAttributeMaxDynamicSharedMemorySize, smem_sq);
    cudaFuncSetAttribute(gemm_tc<128,64,32,32,false>,
                         cudaFuncAttributeMaxDynamicSharedMemorySize, smem_pv);

    // 1) mean pool + gates
    xmean_kernel<<<(Bdim * Ddim + 255) / 256, 256>>>(x);
    prep_kernel<<<1, 256>>>(Wg, bg, hw, temp);

    // 2) projections: q/k/v[s,b] = x[b] @ W[s]^T   (z = s*B + b)
    dim3 gproj(Ndim / 128, Ndim / 128, Sdim * Bdim);
    gemm_tc<128,128,64,32,true><<<gproj, 256, smem_sq>>>(
        x, Wq, q, nullptr, Ddim, Ddim, Ddim, Ddim,
        Bdim, ND, 0LL, 0LL, DD, ND, (long long)Bdim * ND, 1.0f);
    gemm_tc<128,128,64,32,true><<<gproj, 256, smem_sq>>>(
        x, Wk, k, nullptr, Ddim, Ddim, Ddim, Ddim,
        Bdim, ND, 0LL, 0LL, DD, ND, (long long)Bdim * ND, 1.0f);
    gemm_tc<128,128,64,32,true><<<gproj, 256, smem_sq>>>(
        x, Wv, v, nullptr, Ddim, Ddim, Ddim, Ddim,
        Bdim, ND, 0LL, 0LL, DD, ND, (long long)Bdim * ND, 1.0f);

    // 3) dots[s,b,h] = scale * Q K^T   (z = sb*H + h, zmod=H)
    dim3 gdots(Ndim / 128, Ndim / 128, Sdim * Bdim * Hdim);
    gemm_tc<128,128,64,32,true><<<gdots, 256, smem_sq>>>(
        q, k, p, nullptr, DHdim, Ddim, Ddim, Ndim,
        Hdim, (long long)DHdim, ND, (long long)DHdim, ND,
        (long long)NNdim, (long long)Hdim * NNdim, 0.125f);

    // 4) softmax rows (temp folded in)
    softmax_kernel<<<Sdim * Bdim * Hdim * Ndim, 256>>>();

    // 5) combined_attn mean over h -> second output
    reduce_attn_kernel<<<(unsigned)((Bdim * (long long)NNdim + 255) / 256), 256>>>(
        out + (long long)Bdim * ND);

    // 6) outs[s,b,h] = P @ V   (M=1024, N=64 non-transposed B, K=1024)
    dim3 gpv(1, Ndim / 128, Sdim * Bdim * Hdim);
    gemm_tc<128,64,32,32,false><<<gpv, 256, smem_pv>>>(
        p, v, outs, nullptr, Ndim, Ndim, Ddim, Ddim,
        Hdim, (long long)NNdim, (long long)Hdim * NNdim,
        (long long)DHdim, ND, (long long)DHdim, ND, 1.0f);

    // 7) gate + hypothesis combine
    combine_kernel<<<(unsigned)((Bdim * ND + 255) / 256), 256>>>();

    // 8) y = combined @ Wo^T + bo -> first output
    dim3 gfin(Ndim / 128, Ndim / 128, Bdim);
    gemm_tc<128,128,64,32,true><<<gfin, 256, smem_sq>>>(
        comb, Wo, out, bo, Ddim, Ddim, Ddim, Ddim,
        1, 0LL, ND, 0LL, 0LL, 0LL, ND, 1.0f);
}

// round 6
// speedup vs baseline: 3.3788x; 1.0917x over previous
#include <cuda_runtime.h>
#include <cuda_fp16.h>
#include <math.h>

#define Bdim 2
#define Ndim 1024
#define Ddim 1024
#define Hdim 16
#define Sdim 4
#define DHdim 64
#define NNdim (Ndim*Ndim)
#define KT 32

// ---------------- static scratch (no allocation allowed) ----------------
__device__ float  g_q[Sdim*Bdim*Ndim*Ddim];           // 32 MB
__device__ float  g_k[Sdim*Bdim*Ndim*Ddim];           // 32 MB
__device__ float  g_v[Sdim*Bdim*Ndim*Ddim];           // 32 MB
__device__ float  g_p[(size_t)Sdim*Bdim*Hdim*NNdim];  // 512 MB raw dots (fp32)
__device__ __half g_ph[(size_t)Sdim*Bdim*Hdim*NNdim]; // 256 MB probs (fp16)
__device__ float  g_comb[Bdim*Ndim*Ddim];             // 8 MB combined
__device__ float  g_xmean[Bdim*Ddim];
__device__ float  g_params[16];                       // [0]=1/temp, [1..4]=gw, [5..12]=coh[b][s]

// ---------------- helpers ----------------
__device__ __forceinline__ unsigned f2tf32(float x) {
    unsigned u;
    asm("cvt.rna.tf32.f32 %0, %1;" : "=r"(u) : "f"(x));
    return u;
}

__device__ __forceinline__ void mma_tf32(float* d, const unsigned* a, const unsigned* b) {
    asm volatile(
        "mma.sync.aligned.m16n8k8.row.col.f32.tf32.tf32.f32 "
        "{%0,%1,%2,%3},{%4,%5,%6,%7},{%8,%9},{%0,%1,%2,%3};"
        : "+f"(d[0]), "+f"(d[1]), "+f"(d[2]), "+f"(d[3])
        : "r"(a[0]), "r"(a[1]), "r"(a[2]), "r"(a[3]), "r"(b[0]), "r"(b[1]));
}

// ---------------- mean pool over tokens ----------------
__global__ void xmean_kernel(const float* __restrict__ x) {
    int idx = blockIdx.x * blockDim.x + threadIdx.x;  // b*D + d
    if (idx >= Bdim * Ddim) return;
    int b = idx / Ddim, d = idx % Ddim;
    const float* p = x + (long long)b * Ndim * Ddim + d;
    float acc = 0.f;
    for (int n = 0; n < Ndim; n++) acc += p[(long long)n * Ddim];
    g_xmean[idx] = acc * (1.0f / Ndim);
}

// ---------------- temp clip, gate weights, coherence gate ----------------
__global__ void prep_kernel(const float* __restrict__ Wg, const float* __restrict__ bg,
                            const float* __restrict__ hyp_w,
                            const float* __restrict__ temperature) {
    int t = threadIdx.x;
    int warp = t / 32, lane = t % 32;
    if (warp < Bdim * Sdim) {
        int b = warp / Sdim, s = warp % Sdim;
        float acc = 0.f;
        for (int d = lane; d < Ddim; d += 32)
            acc += g_xmean[b * Ddim + d] * Wg[s * Ddim + d];
        #pragma unroll
        for (int o = 16; o > 0; o >>= 1) acc += __shfl_down_sync(0xffffffff, acc, o);
        if (lane == 0) {
            float vv = acc + bg[s];
            g_params[5 + b * Sdim + s] = 1.0f / (1.0f + expf(-vv));
        }
    }
    if (t == 0) {
        float tp = fminf(fmaxf(temperature[0], 0.1f), 10.0f);
        g_params[0] = 1.0f / tp;
        float hw[Sdim];
        float m = -1e30f;
        for (int s = 0; s < Sdim; s++) { hw[s] = hyp_w[s] / tp; m = fmaxf(m, hw[s]); }
        float sum = 0.f;
        for (int s = 0; s < Sdim; s++) { hw[s] = expf(hw[s] - m); sum += hw[s]; }
        for (int s = 0; s < Sdim; s++) g_params[1 + s] = hw[s] / sum;
    }
}

// ---------------- tensor-core batched C = alpha * A * B^T (+bias), 512 thr ----------------
// A: [M,K] row-major (lda), Bt: [N,K] row-major (ldb), C: [M,N] row-major (ldc)
// offsets: offX = (z % zmod)*sXlo + (z / zmod)*sXhi
__global__ void __launch_bounds__(512) gemm_tc512(
    const float* __restrict__ Aall, const float* __restrict__ Ball,
    float* __restrict__ Call, const float* __restrict__ bias,
    int K, int lda, int ldb, int ldc,
    int zmod, long long sAlo, long long sAhi,
    long long sBlo, long long sBhi, long long sClo, long long sChi, float alpha)
{
    constexpr int BM = 128, BN = 128, WM = 32, WN = 32;
    constexpr int MT = WM / 16, NT = WN / 8;   // 2, 4
    constexpr int LDP = 36;
    constexpr int RPP = 512 / 8;               // 64 rows per pass
    constexpr int AI = BM / RPP, BI = BN / RPP; // 2, 2

    extern __shared__ float sm[];
    float* As = sm;                    // [2][BM][LDP]
    float* Bs = sm + 2 * BM * LDP;     // [2][BN][LDP]

    int z = blockIdx.z;
    const float* A  = Aall + (long long)(z % zmod) * sAlo + (long long)(z / zmod) * sAhi;
    const float* Bt = Ball + (long long)(z % zmod) * sBlo + (long long)(z / zmod) * sBhi;
    float* C = Call + (long long)(z % zmod) * sClo + (long long)(z / zmod) * sChi;

    int m0 = blockIdx.y * BM;
    int n0 = blockIdx.x * BN;
    int t = threadIdx.x;
    int lane = t & 31, w = t >> 5;
    int wr = w / (BN / WN), wc = w % (BN / WN);   // 0..3, 0..3
    int lcol = (t & 7) * 4;
    int lrow = t >> 3;

    float acc[MT][NT][4];
    #pragma unroll
    for (int mt = 0; mt < MT; mt++)
        #pragma unroll
        for (int nt = 0; nt < NT; nt++)
            #pragma unroll
            for (int i = 0; i < 4; i++) acc[mt][nt][i] = 0.f;

    const int numT = K / KT;
    float4 ra[AI], rb[BI];

    auto loadG = [&](int kt) {
        #pragma unroll
        for (int i = 0; i < AI; i++) {
            int r = lrow + i * RPP;
            ra[i] = *(const float4*)(A + (long long)(m0 + r) * lda + kt * KT + lcol);
        }
        #pragma unroll
        for (int i = 0; i < BI; i++) {
            int r = lrow + i * RPP;
            rb[i] = *(const float4*)(Bt + (long long)(n0 + r) * ldb + kt * KT + lcol);
        }
    };
    auto storeS = [&](int buf) {
        #pragma unroll
        for (int i = 0; i < AI; i++) {
            int r = lrow + i * RPP;
            unsigned* d = (unsigned*)(As + buf * BM * LDP + r * LDP + lcol);
            d[0] = f2tf32(ra[i].x); d[1] = f2tf32(ra[i].y);
            d[2] = f2tf32(ra[i].z); d[3] = f2tf32(ra[i].w);
        }
        #pragma unroll
        for (int i = 0; i < BI; i++) {
            int r = lrow + i * RPP;
            unsigned* d = (unsigned*)(Bs + buf * BN * LDP + r * LDP + lcol);
            d[0] = f2tf32(rb[i].x); d[1] = f2tf32(rb[i].y);
            d[2] = f2tf32(rb[i].z); d[3] = f2tf32(rb[i].w);
        }
    };

    loadG(0);
    storeS(0);

    int g = lane >> 2, c4 = lane & 3;
    for (int kt = 0; kt < numT; kt++) {
        __syncthreads();
        int buf = kt & 1;
        if (kt + 1 < numT) loadG(kt + 1);

        const float* Ab = As + buf * BM * LDP;
        const float* Bb = Bs + buf * BN * LDP;
        #pragma unroll
        for (int ks = 0; ks < KT / 8; ks++) {
            int kb = ks * 8 + c4;
            unsigned afr[MT][4], bfr[NT][2];
            #pragma unroll
            for (int mt = 0; mt < MT; mt++) {
                const float* pA = Ab + (wr * WM + mt * 16 + g) * LDP;
                afr[mt][0] = __float_as_uint(pA[kb]);
                afr[mt][1] = __float_as_uint(pA[8 * LDP + kb]);
                afr[mt][2] = __float_as_uint(pA[kb + 4]);
                afr[mt][3] = __float_as_uint(pA[8 * LDP + kb + 4]);
            }
            #pragma unroll
            for (int nt = 0; nt < NT; nt++) {
                const float* pB = Bb + (wc * WN + nt * 8 + g) * LDP;
                bfr[nt][0] = __float_as_uint(pB[kb]);
                bfr[nt][1] = __float_as_uint(pB[kb + 4]);
            }
            #pragma unroll
            for (int mt = 0; mt < MT; mt++)
                #pragma unroll
                for (int nt = 0; nt < NT; nt++)
                    mma_tf32(acc[mt][nt], afr[mt], bfr[nt]);
        }
        if (kt + 1 < numT) storeS(1 - buf);
    }

    #pragma unroll
    for (int mt = 0; mt < MT; mt++) {
        int r = m0 + wr * WM + mt * 16 + g;
        #pragma unroll
        for (int nt = 0; nt < NT; nt++) {
            int c = n0 + wc * WN + nt * 8 + c4 * 2;
            float b0 = 0.f, b1 = 0.f;
            if (bias) { b0 = bias[c]; b1 = bias[c + 1]; }
            float2 v0 = make_float2(acc[mt][nt][0] * alpha + b0,
                                    acc[mt][nt][1] * alpha + b1);
            float2 v1 = make_float2(acc[mt][nt][2] * alpha + b0,
                                    acc[mt][nt][3] * alpha + b1);
            *(float2*)(C + (long long)r * ldc + c) = v0;
            *(float2*)(C + (long long)(r + 8) * ldc + c) = v1;
        }
    }
}

// ---------------- softmax: fp32 dots -> fp16 probs ----------------
__global__ void softmax_kernel() {
    long long row = blockIdx.x;
    int t = threadIdx.x;
    int lane = t & 31, warp = t >> 5;
    const float4* src = (const float4*)(g_p + row * Ndim);
    float4 v = src[t];
    float invT = g_params[0];
    v.x *= invT; v.y *= invT; v.z *= invT; v.w *= invT;

    __shared__ float red[16];
    float mx = fmaxf(fmaxf(v.x, v.y), fmaxf(v.z, v.w));
    #pragma unroll
    for (int o = 16; o > 0; o >>= 1) mx = fmaxf(mx, __shfl_xor_sync(0xffffffff, mx, o));
    if (lane == 0) red[warp] = mx;
    __syncthreads();
    float m = -1e30f;
    #pragma unroll
    for (int i = 0; i < 8; i++) m = fmaxf(m, red[i]);

    float4 e;
    e.x = __expf(v.x - m); e.y = __expf(v.y - m);
    e.z = __expf(v.z - m); e.w = __expf(v.w - m);
    float sm = e.x + e.y + e.z + e.w;
    #pragma unroll
    for (int o = 16; o > 0; o >>= 1) sm += __shfl_xor_sync(0xffffffff, sm, o);
    if (lane == 0) red[8 + warp] = sm;
    __syncthreads();
    float tot = 0.f;
    #pragma unroll
    for (int i = 0; i < 8; i++) tot += red[8 + i];
    float inv = 1.0f / tot;

    __half2 h01 = __floats2half2_rn(e.x * inv, e.y * inv);
    __half2 h23 = __floats2half2_rn(e.z * inv, e.w * inv);
    uint2 u;
    u.x = *(unsigned*)&h01; u.y = *(unsigned*)&h23;
    ((uint2*)(g_ph + row * Ndim))[t] = u;
}

// ---------------- combined_attn.mean(h): out2[b,i,j] = (1/H) sum_{s,h} gw[s] p ----------------
__global__ void reduce_attn_kernel(float* __restrict__ outAttn) {
    long long idx = (long long)blockIdx.x * blockDim.x + threadIdx.x;  // groups of 4
    if (idx >= (long long)Bdim * NNdim / 4) return;
    int b = (int)(idx / (NNdim / 4));
    long long rem = (idx % (NNdim / 4)) * 4;
    float a0 = 0.f, a1 = 0.f, a2 = 0.f, a3 = 0.f;
    #pragma unroll
    for (int s = 0; s < Sdim; s++) {
        float gwv = g_params[1 + s];
        const __half* base = g_ph + ((long long)(s * Bdim + b) * Hdim) * NNdim + rem;
        float h0 = 0.f, h1 = 0.f, h2 = 0.f, h3 = 0.f;
        #pragma unroll 4
        for (int h = 0; h < Hdim; h++) {
            uint2 u = *(const uint2*)(base + (long long)h * NNdim);
            __half2 p01 = *(__half2*)&u.x, p23 = *(__half2*)&u.y;
            float2 f01 = __half22float2(p01), f23 = __half22float2(p23);
            h0 += f01.x; h1 += f01.y; h2 += f23.x; h3 += f23.y;
        }
        a0 += gwv * h0; a1 += gwv * h1; a2 += gwv * h2; a3 += gwv * h3;
    }
    float4 o = make_float4(a0 * (1.0f / Hdim), a1 * (1.0f / Hdim),
                           a2 * (1.0f / Hdim), a3 * (1.0f / Hdim));
    *(float4*)(outAttn + idx * 4) = o;
}

// ---------------- fused P@V + per-sample gate + hypothesis combine ----------------
// block: (i-tile of 128 rows, b*H + h). Loops s=0..3 accumulating w_s * (P_s @ V_s).
// Writes g_comb[b, i, h*64+dh] directly.
__global__ void __launch_bounds__(256) pv_combine_kernel() {
    constexpr int BM = 128, BN = 64, WM = 32, WN = 32;
    constexpr int MT = 2, NT = 4;
    constexpr int LDP = 36, LDB2 = 72;
    constexpr int BSZ = KT * LDB2;

    extern __shared__ float sm[];
    float* As = sm;                   // [2][128][36]
    float* Bs = sm + 2 * BM * LDP;    // [2][32][72]

    int zz = blockIdx.y;
    int b = zz / Hdim, h = zz % Hdim;
    int m0 = blockIdx.x * BM;

    int t = threadIdx.x;
    int lane = t & 31, w = t >> 5;
    int wr = w / (BN / WN), wc = w % (BN / WN);   // 0..3, 0..1
    int lcol = (t & 7) * 4;    // half col within K-tile
    int lrow = t >> 3;         // 0..31
    int bcol = (t % 16) * 4;   // V: n col (floats)
    int browk = t / 16;        // V: k row 0..15
    int g = lane >> 2, c4 = lane & 3;

    float acc[MT][NT][4];
    #pragma unroll
    for (int mt = 0; mt < MT; mt++)
        #pragma unroll
        for (int nt = 0; nt < NT; nt++)
            #pragma unroll
            for (int i = 0; i < 4; i++) acc[mt][nt][i] = 0.f;

    for (int s = 0; s < Sdim; s++) {
        const __half* A = g_ph + (size_t)((s * Bdim + b) * Hdim + h) * NNdim;
        const float* V = g_v + (size_t)(s * Bdim + b) * Ndim * Ddim + h * DHdim;
        float ws = g_params[1 + s] * g_params[5 + b * Sdim + s];

        uint2 ua[4];
        float4 rbv[2];
        auto loadG = [&](int kt) {
            #pragma unroll
            for (int i = 0; i < 4; i++) {
                int r = lrow + i * 32;
                ua[i] = *(const uint2*)(A + (size_t)(m0 + r) * Ndim + kt * KT + lcol);
            }
            #pragma unroll
            for (int i = 0; i < 2; i++) {
                int kk = browk + i * 16;
                rbv[i] = *(const float4*)(V + (size_t)(kt * KT + kk) * Ddim + bcol);
            }
        };
        auto storeS = [&](int buf) {
            #pragma unroll
            for (int i = 0; i < 4; i++) {
                int r = lrow + i * 32;
                __half2 p01 = *(__half2*)&ua[i].x, p23 = *(__half2*)&ua[i].y;
                float2 f01 = __half22float2(p01), f23 = __half22float2(p23);
                unsigned* d = (unsigned*)(As + buf * BM * LDP + r * LDP + lcol);
                d[0] = f2tf32(f01.x * ws); d[1] = f2tf32(f01.y * ws);
                d[2] = f2tf32(f23.x * ws); d[3] = f2tf32(f23.y * ws);
            }
            #pragma unroll
            for (int i = 0; i < 2; i++) {
                int kk = browk + i * 16;
                unsigned* d = (unsigned*)(Bs + buf * BSZ + kk * LDB2 + bcol);
                d[0] = f2tf32(rbv[i].x); d[1] = f2tf32(rbv[i].y);
                d[2] = f2tf32(rbv[i].z); d[3] = f2tf32(rbv[i].w);
            }
        };

        const int numT = Ndim / KT;   // 32
        loadG(0);
        if (s > 0) __syncthreads();   // previous segment's smem fully consumed
        storeS(0);
        for (int kt = 0; kt < numT; kt++) {
            __syncthreads();
            int buf = kt & 1;
            if (kt + 1 < numT) loadG(kt + 1);

            const float* Ab = As + buf * BM * LDP;
            const float* Bb = Bs + buf * BSZ;
            #pragma unroll
            for (int ks = 0; ks < KT / 8; ks++) {
                int kb = ks * 8 + c4;
                unsigned afr[MT][4], bfr[NT][2];
                #pragma unroll
                for (int mt = 0; mt < MT; mt++) {
                    const float* pA = Ab + (wr * WM + mt * 16 + g) * LDP;
                    afr[mt][0] = __float_as_uint(pA[kb]);
                    afr[mt][1] = __float_as_uint(pA[8 * LDP + kb]);
                    afr[mt][2] = __float_as_uint(pA[kb + 4]);
                    afr[mt][3] = __float_as_uint(pA[8 * LDP + kb + 4]);
                }
                #pragma unroll
                for (int nt = 0; nt < NT; nt++) {
                    int n = wc * WN + nt * 8 + g;
                    bfr[nt][0] = __float_as_uint(Bb[kb * LDB2 + n]);
                    bfr[nt][1] = __float_as_uint(Bb[(kb + 4) * LDB2 + n]);
                }
                #pragma unroll
                for (int mt = 0; mt < MT; mt++)
                    #pragma unroll
                    for (int nt = 0; nt < NT; nt++)
                        mma_tf32(acc[mt][nt], afr[mt], bfr[nt]);
            }
            if (kt + 1 < numT) storeS(1 - buf);
        }
    }

    // epilogue -> g_comb[b, r, h*64 + c]
    float* C = g_comb + (size_t)b * Ndim * Ddim + h * DHdim;
    #pragma unroll
    for (int mt = 0; mt < MT; mt++) {
        int r = m0 + wr * WM + mt * 16 + g;
        #pragma unroll
        for (int nt = 0; nt < NT; nt++) {
            int c = wc * WN + nt * 8 + c4 * 2;
            *(float2*)(C + (size_t)r * Ddim + c) =
                make_float2(acc[mt][nt][0], acc[mt][nt][1]);
            *(float2*)(C + (size_t)(r + 8) * Ddim + c) =
                make_float2(acc[mt][nt][2], acc[mt][nt][3]);
        }
    }
}

// ---------------- launch ----------------
extern "C" void kernel_launch(void* const* d_in, const int* in_sizes, int n_in,
                              void* d_out, int out_size) {
    const float* x    = (const float*)d_in[0];
    const float* Wq   = (const float*)d_in[1];
    const float* Wk   = (const float*)d_in[2];
    const float* Wv   = (const float*)d_in[3];
    const float* Wg   = (const float*)d_in[4];
    const float* bg   = (const float*)d_in[5];
    const float* Wo   = (const float*)d_in[6];
    const float* bo   = (const float*)d_in[7];
    const float* hw   = (const float*)d_in[8];
    const float* temp = (const float*)d_in[9];
    float* out = (float*)d_out;

    float *q, *k, *v, *comb, *p;
    cudaGetSymbolAddress((void**)&q, g_q);
    cudaGetSymbolAddress((void**)&k, g_k);
    cudaGetSymbolAddress((void**)&v, g_v);
    cudaGetSymbolAddress((void**)&comb, g_comb);
    cudaGetSymbolAddress((void**)&p, g_p);

    const long long ND = (long long)Ndim * Ddim;
    const long long DD = (long long)Ddim * Ddim;

    const int smem_sq = 2 * (128 + 128) * 36 * (int)sizeof(float);          // 73728
    const int smem_pv = (2 * 128 * 36 + 2 * KT * 72) * (int)sizeof(float);  // 55296
    cudaFuncSetAttribute(gemm_tc512,
                         cudaFuncAttributeMaxDynamicSharedMemorySize, smem_sq);
    cudaFuncSetAttribute(pv_combine_kernel,
                         cudaFuncAttributeMaxDynamicSharedMemorySize, smem_pv);

    // 1) mean pool + gates (weights needed by softmax/reduce/pv)
    xmean_kernel<<<(Bdim * Ddim + 255) / 256, 256>>>(x);
    prep_kernel<<<1, 256>>>(Wg, bg, hw, temp);

    // 2) projections: q/k/v[s,b] = x[b] @ W[s]^T   (z = s*B + b)
    dim3 gproj(Ndim / 128, Ndim / 128, Sdim * Bdim);
    gemm_tc512<<<gproj, 512, smem_sq>>>(
        x, Wq, q, nullptr, Ddim, Ddim, Ddim, Ddim,
        Bdim, ND, 0LL, 0LL, DD, ND, (long long)Bdim * ND, 1.0f);
    gemm_tc512<<<gproj, 512, smem_sq>>>(
        x, Wk, k, nullptr, Ddim, Ddim, Ddim, Ddim,
        Bdim, ND, 0LL, 0LL, DD, ND, (long long)Bdim * ND, 1.0f);
    gemm_tc512<<<gproj, 512, smem_sq>>>(
        x, Wv, v, nullptr, Ddim, Ddim, Ddim, Ddim,
        Bdim, ND, 0LL, 0LL, DD, ND, (long long)Bdim * ND, 1.0f);

    // 3) dots[s,b,h] = scale * Q K^T   (z = sb*H + h, zmod=H)
    dim3 gdots(Ndim / 128, Ndim / 128, Sdim * Bdim * Hdim);
    gemm_tc512<<<gdots, 512, smem_sq>>>(
        q, k, p, nullptr, DHdim, Ddim, Ddim, Ndim,
        Hdim, (long long)DHdim, ND, (long long)DHdim, ND,
        (long long)NNdim, (long long)Hdim * NNdim, 0.125f);

    // 4) softmax rows: fp32 dots -> fp16 probs
    softmax_kernel<<<Sdim * Bdim * Hdim * Ndim, 256>>>();

    // 5) combined_attn mean over h -> second output
    reduce_attn_kernel<<<(unsigned)((Bdim * (long long)NNdim / 4 + 255) / 256), 256>>>(
        out + (long long)Bdim * ND);

    // 6) fused P@V + gate + combine -> g_comb
    dim3 gpv(Ndim / 128, Bdim * Hdim);
    pv_combine_kernel<<<gpv, 256, smem_pv>>>();

    // 7) y = combined @ Wo^T + bo -> first output
    dim3 gfin(Ndim / 128, Ndim / 128, Bdim);
    gemm_tc512<<<gfin, 512, smem_sq>>>(
        comb, Wo, out, bo, Ddim, Ddim, Ddim, Ddim,
        1, 0LL, ND, 0LL, 0LL, 0LL, ND, 1.0f);
}